// round 9
// baseline (speedup 1.0000x reference)
#include <cuda_runtime.h>
#include <cuda_fp16.h>
#include <cstdint>
#include <math.h>

#define NB 8
#define NC 32
#define NR 2048
#define NI 64
#define NO 64
#define RT 16                 // r-values per priors block
#define RS 2                  // r-values per pipeline stage (32 KB W slab)
#define NSTAGE (RT / RS)      // 8
#define NQ 4                  // R-split quarters in iter_kernel

// dynamic smem layout (bytes): W 2x32KB | x 2x4KB | mbar
#define SMEM_W     0
#define SMEM_X     65536
#define SMEM_MBAR  73728
#define SMEM_TOTAL 73760

#define TOT (NB * NC * NO)    // 16384

// Scratch (static device globals — no allocation in kernel_launch)
__device__ __half g_ph[NB * NC * NR * NO];      // 67 MB fp16 priors -> L2 resident
__device__ float  g_w[TOT];                     // cumulative v (logit weight)
__device__ float  g_pden[NQ * TOT];             // per-quarter softmax denominators
__device__ float  g_pnum[NQ * TOT];             // per-quarter numerators; [0] also = sum_r priors

// ---------------------------------------------------------------------------
__device__ __forceinline__ unsigned sptr(const void* p) {
    return (unsigned)__cvta_generic_to_shared(p);
}
__device__ __forceinline__ void mbar_init(unsigned m, unsigned cnt) {
    asm volatile("mbarrier.init.shared.b64 [%0], %1;" :: "r"(m), "r"(cnt) : "memory");
}
__device__ __forceinline__ void mbar_expect(unsigned m, unsigned bytes) {
    asm volatile("mbarrier.arrive.expect_tx.shared.b64 _, [%0], %1;"
                 :: "r"(m), "r"(bytes) : "memory");
}
__device__ __forceinline__ void bulk_g2s(unsigned dst, const void* src,
                                         unsigned bytes, unsigned m) {
    asm volatile("cp.async.bulk.shared::cta.global.mbarrier::complete_tx::bytes "
                 "[%0], [%1], %2, [%3];"
                 :: "r"(dst), "l"(src), "r"(bytes), "r"(m) : "memory");
}
__device__ __forceinline__ void mbar_wait(unsigned m, unsigned ph) {
    asm volatile(
        "{\n\t.reg .pred P;\n\t"
        "W1_%=:\n\t"
        "mbarrier.try_wait.parity.acquire.cta.shared::cta.b64 P, [%0], %1, 0x989680;\n\t"
        "@P bra W2_%=;\n\t"
        "bra W1_%=;\n\t"
        "W2_%=:\n\t}"
        :: "r"(m), "r"(ph) : "memory");
}

// ---- packed f32x2 ops (Blackwell) -----------------------------------------
typedef unsigned long long u64t;
__device__ __forceinline__ u64t fma2(u64t x, u64t w, u64t a) {
    u64t d;
    asm("fma.rn.f32x2 %0, %1, %2, %3;" : "=l"(d) : "l"(x), "l"(w), "l"(a));
    return d;
}
__device__ __forceinline__ u64t add2(u64t a, u64t b) {
    u64t d;
    asm("add.rn.f32x2 %0, %1, %2;" : "=l"(d) : "l"(a), "l"(b));
    return d;
}
__device__ __forceinline__ u64t pack2(float x) {
    u64t d; asm("mov.b64 %0, {%1, %1};" : "=l"(d) : "f"(x)); return d;
}
__device__ __forceinline__ float2 unpk2(u64t v) {
    float2 r; asm("mov.b64 {%0, %1}, %2;" : "=f"(r.x), "=f"(r.y) : "l"(v)); return r;
}

// ---------------------------------------------------------------------------
// Kernel 0: zero the accumulators (g_w and quarter-0 of g_pnum).
// ---------------------------------------------------------------------------
__global__ __launch_bounds__(512) void zero_kernel()
{
    int i = blockIdx.x * 512 + threadIdx.x;
    if (i < TOT) { g_w[i] = 0.0f; g_pnum[i] = 0.0f; }
}

// ---------------------------------------------------------------------------
// Kernel 1: priors[b,c,r,o] = sum_i x[b,c,r,i] * W[c,r,i,o], fp16 store.
// TMA bulk double-buffered pipeline; per stage one 32 KB W slab + 8 x rows.
// Inner math in packed f32x2 (FFMA2): per i, 1 pack + 4 FMA2 covers 8 outputs
// -> FMA-pipe load halved vs scalar FFMA; DRAM becomes the only near-critical
// pipe. Fuses iteration-0 sum via atomics.
// Block: 128 threads = rj(2) x b(8) x og(8); thread computes 1 batch x
// 8 outputs (o = 8*og..8*og+7) for r = r0 + RS*s + rj.
// ---------------------------------------------------------------------------
__global__ __launch_bounds__(128) void priors_kernel(
    const float* __restrict__ x, const float* __restrict__ Wt)
{
    extern __shared__ float sm[];
    float* sW = sm;                          // [2][RS*NI*NO]
    float* sX = sm + SMEM_X / 4;             // [2][NB][RS*NI]
    const unsigned smb = sptr(sm);
    const unsigned mb0 = smb + SMEM_MBAR;
    const unsigned mb1 = mb0 + 8;

    const int c  = blockIdx.y;
    const int r0 = blockIdx.x * RT;
    const int t  = threadIdx.x;
    const int og = t & 7;
    const int bb = (t >> 3) & 7;
    const int rj = t >> 6;

    if (t == 0) { mbar_init(mb0, 1); mbar_init(mb1, 1); }
    __syncthreads();

    // stage loader: 32 KB W slab + 8 x-rows (512 B each)
    auto load_stage = [&](int s, int buf, unsigned m) {
        mbar_expect(m, 32768 + NB * RS * NI * 4);
        bulk_g2s(smb + SMEM_W + buf * 32768,
                 Wt + (size_t)(c * NR + r0 + s * RS) * (NI * NO), 32768, m);
#pragma unroll
        for (int b = 0; b < NB; b++)
            bulk_g2s(smb + SMEM_X + buf * (NB * RS * NI * 4) + b * (RS * NI * 4),
                     x + (size_t)((b * NC + c) * NR + r0 + s * RS) * NI,
                     RS * NI * 4, m);
    };

    if (t == 0) load_stage(0, 0, mb0);

    unsigned ph0 = 0, ph1 = 0;
    u64t ms0 = 0ull, ms1 = 0ull, ms2 = 0ull, ms3 = 0ull;   // packed (0,0)

    for (int s = 0; s < NSTAGE; s++) {
        const int buf = s & 1;

        // prefetch next stage (other buffer freed by syncthreads at s-1 end)
        if (t == 0 && s + 1 < NSTAGE)
            load_stage(s + 1, (s + 1) & 1, ((s + 1) & 1) ? mb1 : mb0);

        if (buf == 0) { mbar_wait(mb0, ph0); ph0 ^= 1; }
        else          { mbar_wait(mb1, ph1); ph1 ^= 1; }

        const float* Wb = sW + buf * (RS * NI * NO) + rj * (NI * NO) + og * 8;
        const float* xr = sX + buf * (NB * RS * NI) + (bb * RS + rj) * NI;

        u64t a0 = 0ull, a1 = 0ull, a2 = 0ull, a3 = 0ull;

#pragma unroll
        for (int i = 0; i < NI; i++) {
            u64t xp = pack2(xr[i]);
            const ulonglong2* wp = (const ulonglong2*)(Wb + i * NO);
            ulonglong2 wA = wp[0];          // o pairs (0,1),(2,3)
            ulonglong2 wB = wp[1];          // o pairs (4,5),(6,7)
            a0 = fma2(xp, wA.x, a0);
            a1 = fma2(xp, wA.y, a1);
            a2 = fma2(xp, wB.x, a2);
            a3 = fma2(xp, wB.y, a3);
        }

        // fp16 store: 8 outputs = 16 B
        const int r = r0 + s * RS + rj;
        {
            float2 f0 = unpk2(a0), f1 = unpk2(a1), f2 = unpk2(a2), f3 = unpk2(a3);
            union { uint4 u; __half2 h[4]; } pk;
            pk.h[0] = __floats2half2_rn(f0.x, f0.y);
            pk.h[1] = __floats2half2_rn(f1.x, f1.y);
            pk.h[2] = __floats2half2_rn(f2.x, f2.y);
            pk.h[3] = __floats2half2_rn(f3.x, f3.y);
            *(uint4*)(g_ph + (size_t)((bb * NC + c) * NR + r) * NO + og * 8) = pk.u;
        }

        ms0 = add2(ms0, a0); ms1 = add2(ms1, a1);
        ms2 = add2(ms2, a2); ms3 = add2(ms3, a3);

        __syncthreads();     // stage buffers free for reuse
    }

    // iteration-0 fusion: sum_r priors -> g_pnum quarter 0
    {
        float* d = g_pnum + (bb * NC + c) * NO + og * 8;
        float2 f0 = unpk2(ms0), f1 = unpk2(ms1), f2 = unpk2(ms2), f3 = unpk2(ms3);
        atomicAdd(d + 0, f0.x); atomicAdd(d + 1, f0.y);
        atomicAdd(d + 2, f1.x); atomicAdd(d + 3, f1.y);
        atomicAdd(d + 4, f2.x); atomicAdd(d + 5, f2.y);
        atomicAdd(d + 6, f3.x); atomicAdd(d + 7, f3.y);
    }
}

// ---------------------------------------------------------------------------
// Kernel 2: one routing iteration (branch-free: |w|<=2, |p|<~16 -> exp safe).
// Grid = NQ blocks per (b,c), 512 rows each; partials to scratch quarters.
// ---------------------------------------------------------------------------
__global__ __launch_bounds__(512) void iter_kernel()
{
    const int blk = blockIdx.x;
    const int bc  = blk >> 2;
    const int qq  = blk & 3;
    const int t   = threadIdx.x;
    const int o4  = t & 15;
    const int g   = t >> 4;

    const uint2* p2 = (const uint2*)(g_ph + (size_t)bc * NR * NO)
                      + (size_t)qq * (NR / NQ) * 16;
    const float4 wv = ((const float4*)g_w)[bc * 16 + o4];

    float d0 = 0.f, d1 = 0.f, d2 = 0.f, d3 = 0.f;
    float n0 = 0.f, n1 = 0.f, n2 = 0.f, n3 = 0.f;

#pragma unroll
    for (int k = 0; k < NR / NQ / 32; k++) {      // 16
        uint2 u = p2[(size_t)(g + 32 * k) * 16 + o4];
        float2 pa = __half22float2(*(__half2*)&u.x);
        float2 pb = __half22float2(*(__half2*)&u.y);
        float e;
        e = __expf(pa.x * wv.x); d0 += e; n0 += pa.x * e;
        e = __expf(pa.y * wv.y); d1 += e; n1 += pa.y * e;
        e = __expf(pb.x * wv.z); d2 += e; n2 += pb.x * e;
        e = __expf(pb.y * wv.w); d3 += e; n3 += pb.y * e;
    }

    __shared__ float smr[2][32][64];
    {
        int ob = o4 * 4;
        smr[0][g][ob + 0] = d0; smr[1][g][ob + 0] = n0;
        smr[0][g][ob + 1] = d1; smr[1][g][ob + 1] = n1;
        smr[0][g][ob + 2] = d2; smr[1][g][ob + 2] = n2;
        smr[0][g][ob + 3] = d3; smr[1][g][ob + 3] = n3;
    }
    __syncthreads();

    if (t < 64) {
        float D = 0.f, N = 0.f;
#pragma unroll 8
        for (int g2 = 0; g2 < 32; g2++) {
            D += smr[0][g2][t];
            N += smr[1][g2][t];
        }
        g_pden[qq * TOT + bc * NO + t] = D;
        g_pnum[qq * TOT + bc * NO + t] = N;
    }
}

// ---------------------------------------------------------------------------
// Kernel 3: s -> squash scale -> update w or write out.
// first=1: s = g_pnum[0]/2048 (uniform softmax, fused iteration 0).
// ---------------------------------------------------------------------------
__global__ __launch_bounds__(512) void squash_kernel(float* __restrict__ out,
                                                     int last, int first)
{
    const int t = threadIdx.x;

    float sv[32];
    float acc = 0.f;
#pragma unroll
    for (int q = 0; q < 32; q++) {
        int j = t + 512 * q;
        float s;
        if (first) {
            s = g_pnum[j] * (1.0f / (float)NR);
        } else {
            float D = g_pden[j] + g_pden[TOT + j] + g_pden[2 * TOT + j] + g_pden[3 * TOT + j];
            float N = g_pnum[j] + g_pnum[TOT + j] + g_pnum[2 * TOT + j] + g_pnum[3 * TOT + j];
            s = N / D;
        }
        sv[q] = s;
        acc += s * s;
    }

    __shared__ float red[16];
    __shared__ float s_scale;
#pragma unroll
    for (int off = 16; off > 0; off >>= 1)
        acc += __shfl_xor_sync(0xFFFFFFFFu, acc, off);
    if ((t & 31) == 0) red[t >> 5] = acc;
    __syncthreads();
    if (t < 32) {
        float a = (t < 16) ? red[t] : 0.f;
#pragma unroll
        for (int off = 8; off > 0; off >>= 1)
            a += __shfl_xor_sync(0xFFFFFFFFu, a, off);
        if (t == 0) s_scale = sqrtf(a) / (1.0f + a);
    }
    __syncthreads();
    const float sc = s_scale;

    if (last) {
#pragma unroll
        for (int q = 0; q < 32; q++) out[t + 512 * q] = sv[q] * sc;
    } else {
#pragma unroll
        for (int q = 0; q < 32; q++) g_w[t + 512 * q] += sv[q] * sc;
    }
}

// ---------------------------------------------------------------------------
extern "C" void kernel_launch(void* const* d_in, const int* in_sizes, int n_in,
                              void* d_out, int out_size)
{
    (void)in_sizes; (void)n_in; (void)out_size;
    const float* x  = (const float*)d_in[0];
    const float* Wt = (const float*)d_in[1];
    float* out = (float*)d_out;

    cudaFuncSetAttribute(priors_kernel,
                         cudaFuncAttributeMaxDynamicSharedMemorySize, SMEM_TOTAL);

    zero_kernel<<<32, 512>>>();
    priors_kernel<<<dim3(NR / RT, NC), 128, SMEM_TOTAL>>>(x, Wt);

    squash_kernel<<<1, 512>>>(nullptr, 0, 1);   // w = v0   (iteration 0, fused sum)

    iter_kernel<<<NQ * NB * NC, 512>>>();       // iteration 1
    squash_kernel<<<1, 512>>>(nullptr, 0, 0);   // w = v0 + v1

    iter_kernel<<<NQ * NB * NC, 512>>>();       // iteration 2
    squash_kernel<<<1, 512>>>(out, 1, 0);       // final squash -> output
}

// round 10
// speedup vs baseline: 2.1110x; 2.1110x over previous
#include <cuda_runtime.h>
#include <cuda_fp16.h>
#include <cstdint>
#include <math.h>

#define NB 8
#define NC 32
#define NR 2048
#define NI 64
#define NO 64
#define RT 16                 // r-values per priors block
#define RS 2                  // r-values per pipeline stage (32 KB W slab)
#define NSTAGE (RT / RS)      // 8
#define NSLOT 3               // pipeline ring depth
#define NQ 4                  // R-split quarters in iter_kernel

// dynamic smem layout (bytes): W 3x32KB | x 3x4KB | mbar
#define SMEM_W     0
#define SMEM_X     98304
#define SMEM_MBAR  110592     // full[3] then empty[3], 8B each
#define SMEM_TOTAL 110656

#define STAGE_BYTES (32768 + 4096)

#define TOT (NB * NC * NO)    // 16384

// Scratch (static device globals — no allocation in kernel_launch)
__device__ __half g_ph[NB * NC * NR * NO];      // 67 MB fp16 priors -> L2 resident
__device__ float  g_w[TOT];                     // cumulative v (logit weight)
__device__ float  g_pden[NQ * TOT];             // per-quarter softmax denominators
__device__ float  g_pnum[NQ * TOT];             // per-quarter numerators; [0] also = sum_r priors

// ---------------------------------------------------------------------------
__device__ __forceinline__ unsigned sptr(const void* p) {
    return (unsigned)__cvta_generic_to_shared(p);
}
__device__ __forceinline__ void mbar_init(unsigned m, unsigned cnt) {
    asm volatile("mbarrier.init.shared.b64 [%0], %1;" :: "r"(m), "r"(cnt) : "memory");
}
__device__ __forceinline__ void mbar_expect(unsigned m, unsigned bytes) {
    asm volatile("mbarrier.arrive.expect_tx.shared.b64 _, [%0], %1;"
                 :: "r"(m), "r"(bytes) : "memory");
}
__device__ __forceinline__ void mbar_arrive(unsigned m) {
    asm volatile("mbarrier.arrive.shared.b64 _, [%0];" :: "r"(m) : "memory");
}
__device__ __forceinline__ void bulk_g2s(unsigned dst, const void* src,
                                         unsigned bytes, unsigned m) {
    asm volatile("cp.async.bulk.shared::cta.global.mbarrier::complete_tx::bytes "
                 "[%0], [%1], %2, [%3];"
                 :: "r"(dst), "l"(src), "r"(bytes), "r"(m) : "memory");
}
__device__ __forceinline__ void mbar_wait(unsigned m, unsigned ph) {
    asm volatile(
        "{\n\t.reg .pred P;\n\t"
        "W1_%=:\n\t"
        "mbarrier.try_wait.parity.acquire.cta.shared::cta.b64 P, [%0], %1, 0x989680;\n\t"
        "@P bra W2_%=;\n\t"
        "bra W1_%=;\n\t"
        "W2_%=:\n\t}"
        :: "r"(m), "r"(ph) : "memory");
}

#define FMA4(A, S, W) { (A).x += (S)*(W).x; (A).y += (S)*(W).y; \
                        (A).z += (S)*(W).z; (A).w += (S)*(W).w; }

// ---------------------------------------------------------------------------
// Kernel 0: zero the accumulators (g_w and quarter-0 of g_pnum).
// ---------------------------------------------------------------------------
__global__ __launch_bounds__(512) void zero_kernel()
{
    int i = blockIdx.x * 512 + threadIdx.x;
    if (i < TOT) { g_w[i] = 0.0f; g_pnum[i] = 0.0f; }
}

// ---------------------------------------------------------------------------
// Kernel 1: priors[b,c,r,o] = sum_i x[b,c,r,i] * W[c,r,i,o], fp16 store.
// Warp-decoupled 3-slot TMA ring: producer warp (t=128..159, lane 0) streams
// 36 KB stages; 4 consumer warps wait full[slot], compute, arrive empty[slot]
// per-warp — no block-wide __syncthreads in the loop, so warps drift up to
// 3 stages and TMA stays continuously fed. Fuses iteration-0 sum.
// Consumers: 128 threads = rj(2) x bq(4) x og(16); thread computes 2 batches
// (2bq, 2bq+1) x 4 outputs for r = r0 + RS*s + rj.
// ---------------------------------------------------------------------------
__global__ __launch_bounds__(160) void priors_kernel(
    const float* __restrict__ x, const float* __restrict__ Wt)
{
    extern __shared__ float sm[];
    float* sW = sm;                          // [NSLOT][RS*NI*NO]
    float* sX = sm + SMEM_X / 4;             // [NSLOT][NB][RS*NI]
    const unsigned smb  = sptr(sm);
    const unsigned mful = smb + SMEM_MBAR;         // full[j] = mful + 8j
    const unsigned memp = smb + SMEM_MBAR + 24;    // empty[j] = memp + 8j

    const int c  = blockIdx.y;
    const int r0 = blockIdx.x * RT;
    const int t  = threadIdx.x;

    if (t == 0) {
#pragma unroll
        for (int j = 0; j < NSLOT; j++) {
            mbar_init(mful + 8 * j, 1);     // completed by expect_tx + TMA
            mbar_init(memp + 8 * j, 4);     // 4 consumer-warp arrivals
        }
    }
    __syncthreads();                        // mbarriers visible to all

    if (t >= 128) {
        // ---------------- producer warp ----------------
        if (t == 128) {
            int eph[NSLOT] = {1, 1, 1};     // first empty-wait passes
            for (int s = 0; s < NSTAGE; s++) {
                const int j = s % NSLOT;
                mbar_wait(memp + 8 * j, eph[j]);
                eph[j] ^= 1;
                const unsigned m = mful + 8 * j;
                mbar_expect(m, STAGE_BYTES);
                bulk_g2s(smb + SMEM_W + j * 32768,
                         Wt + (size_t)(c * NR + r0 + s * RS) * (NI * NO),
                         32768, m);
#pragma unroll
                for (int b = 0; b < NB; b++)
                    bulk_g2s(smb + SMEM_X + j * 4096 + b * (RS * NI * 4),
                             x + (size_t)((b * NC + c) * NR + r0 + s * RS) * NI,
                             RS * NI * 4, m);
            }
        }
        return;
    }

    // ---------------- consumer warps ----------------
    const int rj = t >> 6;
    const int bq = (t >> 4) & 3;
    const int og = t & 15;
    const int b0 = 2 * bq, b1 = 2 * bq + 1;
    const int lane0 = ((t & 31) == 0);

    int fph[NSLOT] = {0, 0, 0};
    float4 ms0 = make_float4(0.f, 0.f, 0.f, 0.f);
    float4 ms1 = make_float4(0.f, 0.f, 0.f, 0.f);

    for (int s = 0; s < NSTAGE; s++) {
        const int j = s % NSLOT;
        mbar_wait(mful + 8 * j, fph[j]);
        fph[j] ^= 1;

        const float*  Wb  = sW + j * (RS * NI * NO) + rj * (NI * NO);
        const float4* xr0 = (const float4*)(sX + j * (NB * RS * NI) + (b0 * RS + rj) * NI);
        const float4* xr1 = (const float4*)(sX + j * (NB * RS * NI) + (b1 * RS + rj) * NI);

        float4 a0 = make_float4(0.f, 0.f, 0.f, 0.f);
        float4 a1 = make_float4(0.f, 0.f, 0.f, 0.f);

#pragma unroll
        for (int i4 = 0; i4 < NI / 4; i4++) {
            float4 xv0 = xr0[i4];
            float4 xv1 = xr1[i4];
            const float4* wrow = (const float4*)(Wb + (i4 * 4) * NO) + og;
            float4 w0 = wrow[0];
            float4 w1 = wrow[16];
            float4 w2 = wrow[32];
            float4 w3 = wrow[48];
            FMA4(a0, xv0.x, w0); FMA4(a1, xv1.x, w0);
            FMA4(a0, xv0.y, w1); FMA4(a1, xv1.y, w1);
            FMA4(a0, xv0.z, w2); FMA4(a1, xv1.z, w2);
            FMA4(a0, xv0.w, w3); FMA4(a1, xv1.w, w3);
        }

        const int r = r0 + s * RS + rj;
        {
            union { uint2 u; __half2 h[2]; } pk;
            pk.h[0] = __floats2half2_rn(a0.x, a0.y);
            pk.h[1] = __floats2half2_rn(a0.z, a0.w);
            *(uint2*)(g_ph + (size_t)((b0 * NC + c) * NR + r) * NO + 4 * og) = pk.u;
            pk.h[0] = __floats2half2_rn(a1.x, a1.y);
            pk.h[1] = __floats2half2_rn(a1.z, a1.w);
            *(uint2*)(g_ph + (size_t)((b1 * NC + c) * NR + r) * NO + 4 * og) = pk.u;
        }

        ms0.x += a0.x; ms0.y += a0.y; ms0.z += a0.z; ms0.w += a0.w;
        ms1.x += a1.x; ms1.y += a1.y; ms1.z += a1.z; ms1.w += a1.w;

        __syncwarp();
        if (lane0) mbar_arrive(memp + 8 * j);   // this warp done with slot j
    }

    // iteration-0 fusion: sum_r priors -> g_pnum quarter 0
    float* d0 = g_pnum + (b0 * NC + c) * NO + 4 * og;
    float* d1 = g_pnum + (b1 * NC + c) * NO + 4 * og;
    atomicAdd(d0 + 0, ms0.x); atomicAdd(d0 + 1, ms0.y);
    atomicAdd(d0 + 2, ms0.z); atomicAdd(d0 + 3, ms0.w);
    atomicAdd(d1 + 0, ms1.x); atomicAdd(d1 + 1, ms1.y);
    atomicAdd(d1 + 2, ms1.z); atomicAdd(d1 + 3, ms1.w);
}

// ---------------------------------------------------------------------------
// Kernel 2: one routing iteration (branch-free: |w|<=2, |p|<~16 -> exp safe).
// Grid = NQ blocks per (b,c), 512 rows each; partials to scratch quarters.
// ---------------------------------------------------------------------------
__global__ __launch_bounds__(512) void iter_kernel()
{
    const int blk = blockIdx.x;
    const int bc  = blk >> 2;
    const int qq  = blk & 3;
    const int t   = threadIdx.x;
    const int o4  = t & 15;
    const int g   = t >> 4;

    const uint2* p2 = (const uint2*)(g_ph + (size_t)bc * NR * NO)
                      + (size_t)qq * (NR / NQ) * 16;
    const float4 wv = ((const float4*)g_w)[bc * 16 + o4];

    float d0 = 0.f, d1 = 0.f, d2 = 0.f, d3 = 0.f;
    float n0 = 0.f, n1 = 0.f, n2 = 0.f, n3 = 0.f;

#pragma unroll
    for (int k = 0; k < NR / NQ / 32; k++) {      // 16
        uint2 u = p2[(size_t)(g + 32 * k) * 16 + o4];
        float2 pa = __half22float2(*(__half2*)&u.x);
        float2 pb = __half22float2(*(__half2*)&u.y);
        float e;
        e = __expf(pa.x * wv.x); d0 += e; n0 += pa.x * e;
        e = __expf(pa.y * wv.y); d1 += e; n1 += pa.y * e;
        e = __expf(pb.x * wv.z); d2 += e; n2 += pb.x * e;
        e = __expf(pb.y * wv.w); d3 += e; n3 += pb.y * e;
    }

    __shared__ float smr[2][32][64];
    {
        int ob = o4 * 4;
        smr[0][g][ob + 0] = d0; smr[1][g][ob + 0] = n0;
        smr[0][g][ob + 1] = d1; smr[1][g][ob + 1] = n1;
        smr[0][g][ob + 2] = d2; smr[1][g][ob + 2] = n2;
        smr[0][g][ob + 3] = d3; smr[1][g][ob + 3] = n3;
    }
    __syncthreads();

    if (t < 64) {
        float D = 0.f, N = 0.f;
#pragma unroll 8
        for (int g2 = 0; g2 < 32; g2++) {
            D += smr[0][g2][t];
            N += smr[1][g2][t];
        }
        g_pden[qq * TOT + bc * NO + t] = D;
        g_pnum[qq * TOT + bc * NO + t] = N;
    }
}

// ---------------------------------------------------------------------------
// Kernel 3: s -> squash scale -> update w or write out.
// first=1: s = g_pnum[0]/2048 (uniform softmax, fused iteration 0).
// ---------------------------------------------------------------------------
__global__ __launch_bounds__(512) void squash_kernel(float* __restrict__ out,
                                                     int last, int first)
{
    const int t = threadIdx.x;

    float sv[32];
    float acc = 0.f;
#pragma unroll
    for (int q = 0; q < 32; q++) {
        int j = t + 512 * q;
        float s;
        if (first) {
            s = g_pnum[j] * (1.0f / (float)NR);
        } else {
            float D = g_pden[j] + g_pden[TOT + j] + g_pden[2 * TOT + j] + g_pden[3 * TOT + j];
            float N = g_pnum[j] + g_pnum[TOT + j] + g_pnum[2 * TOT + j] + g_pnum[3 * TOT + j];
            s = N / D;
        }
        sv[q] = s;
        acc += s * s;
    }

    __shared__ float red[16];
    __shared__ float s_scale;
#pragma unroll
    for (int off = 16; off > 0; off >>= 1)
        acc += __shfl_xor_sync(0xFFFFFFFFu, acc, off);
    if ((t & 31) == 0) red[t >> 5] = acc;
    __syncthreads();
    if (t < 32) {
        float a = (t < 16) ? red[t] : 0.f;
#pragma unroll
        for (int off = 8; off > 0; off >>= 1)
            a += __shfl_xor_sync(0xFFFFFFFFu, a, off);
        if (t == 0) s_scale = sqrtf(a) / (1.0f + a);
    }
    __syncthreads();
    const float sc = s_scale;

    if (last) {
#pragma unroll
        for (int q = 0; q < 32; q++) out[t + 512 * q] = sv[q] * sc;
    } else {
#pragma unroll
        for (int q = 0; q < 32; q++) g_w[t + 512 * q] += sv[q] * sc;
    }
}

// ---------------------------------------------------------------------------
extern "C" void kernel_launch(void* const* d_in, const int* in_sizes, int n_in,
                              void* d_out, int out_size)
{
    (void)in_sizes; (void)n_in; (void)out_size;
    const float* x  = (const float*)d_in[0];
    const float* Wt = (const float*)d_in[1];
    float* out = (float*)d_out;

    cudaFuncSetAttribute(priors_kernel,
                         cudaFuncAttributeMaxDynamicSharedMemorySize, SMEM_TOTAL);

    zero_kernel<<<32, 512>>>();
    priors_kernel<<<dim3(NR / RT, NC), 160, SMEM_TOTAL>>>(x, Wt);

    squash_kernel<<<1, 512>>>(nullptr, 0, 1);   // w = v0   (iteration 0, fused sum)

    iter_kernel<<<NQ * NB * NC, 512>>>();       // iteration 1
    squash_kernel<<<1, 512>>>(nullptr, 0, 0);   // w = v0 + v1

    iter_kernel<<<NQ * NB * NC, 512>>>();       // iteration 2
    squash_kernel<<<1, 512>>>(out, 1, 0);       // final squash -> output
}

// round 11
// speedup vs baseline: 2.1145x; 1.0016x over previous
#include <cuda_runtime.h>
#include <cuda_fp16.h>
#include <cstdint>
#include <math.h>

#define NB 8
#define NC 32
#define NR 2048
#define NI 64
#define NO 64
#define RT 16                 // r-values per priors block
#define RS 2                  // r-values per pipeline stage (32 KB W slab)
#define NSTAGE (RT / RS)      // 8
#define NSLOT 3               // pipeline ring depth
#define NQ 4                  // R-split quarters in iter_kernel

// dynamic smem layout (bytes): W 3x32KB | x 3x4KB | mbar
#define SMEM_W     0
#define SMEM_X     98304
#define SMEM_MBAR  110592     // full[3] then empty[3], 8B each
#define SMEM_TOTAL 110656

#define STAGE_BYTES (32768 + 4096)

#define TOT (NB * NC * NO)    // 16384

// Scratch (static device globals — no allocation in kernel_launch)
__device__ __half g_ph[NB * NC * NR * NO];      // 67 MB fp16 priors -> L2 resident
__device__ float  g_w[TOT];                     // cumulative v (logit weight)
__device__ float  g_pden[NQ * TOT];             // per-quarter softmax denominators
__device__ float  g_pnum[NQ * TOT];             // per-quarter numerators; [0] also = sum_r priors

typedef unsigned long long u64t;

// ---------------------------------------------------------------------------
__device__ __forceinline__ unsigned sptr(const void* p) {
    return (unsigned)__cvta_generic_to_shared(p);
}
__device__ __forceinline__ void mbar_init(unsigned m, unsigned cnt) {
    asm volatile("mbarrier.init.shared.b64 [%0], %1;" :: "r"(m), "r"(cnt) : "memory");
}
__device__ __forceinline__ void mbar_expect(unsigned m, unsigned bytes) {
    asm volatile("mbarrier.arrive.expect_tx.shared.b64 _, [%0], %1;"
                 :: "r"(m), "r"(bytes) : "memory");
}
__device__ __forceinline__ void mbar_arrive(unsigned m) {
    asm volatile("mbarrier.arrive.shared.b64 _, [%0];" :: "r"(m) : "memory");
}
__device__ __forceinline__ u64t mkpolicy_evict_first() {
    u64t p;
    asm("createpolicy.fractional.L2::evict_first.b64 %0, 1.0;" : "=l"(p));
    return p;
}
// bulk g2s with L2 evict-first hint: the 1.07 GB W stream must not evict g_ph
__device__ __forceinline__ void bulk_g2s_ef(unsigned dst, const void* src,
                                            unsigned bytes, unsigned m, u64t pol) {
    asm volatile("cp.async.bulk.shared::cta.global.mbarrier::complete_tx::bytes"
                 ".L2::cache_hint [%0], [%1], %2, [%3], %4;"
                 :: "r"(dst), "l"(src), "r"(bytes), "r"(m), "l"(pol) : "memory");
}
__device__ __forceinline__ void mbar_wait(unsigned m, unsigned ph) {
    asm volatile(
        "{\n\t.reg .pred P;\n\t"
        "W1_%=:\n\t"
        "mbarrier.try_wait.parity.acquire.cta.shared::cta.b64 P, [%0], %1, 0x989680;\n\t"
        "@P bra W2_%=;\n\t"
        "bra W1_%=;\n\t"
        "W2_%=:\n\t}"
        :: "r"(m), "r"(ph) : "memory");
}

#define FMA4(A, S, W) { (A).x += (S)*(W).x; (A).y += (S)*(W).y; \
                        (A).z += (S)*(W).z; (A).w += (S)*(W).w; }

// ---------------------------------------------------------------------------
// Kernel 0: zero the accumulators (g_w and quarter-0 of g_pnum).
// ---------------------------------------------------------------------------
__global__ __launch_bounds__(512) void zero_kernel()
{
    int i = blockIdx.x * 512 + threadIdx.x;
    if (i < TOT) { g_w[i] = 0.0f; g_pnum[i] = 0.0f; }
}

// ---------------------------------------------------------------------------
// Kernel 1: priors[b,c,r,o] = sum_i x[b,c,r,i] * W[c,r,i,o], fp16 store.
// Warp-decoupled 3-slot TMA ring; W/x loads tagged L2::evict_first so the
// 1.14 GB stream recycles a small L2 footprint and g_ph stays L2-resident.
// Fuses iteration-0 sum. Consumers: 128 threads = rj(2) x bq(4) x og(16).
// ---------------------------------------------------------------------------
__global__ __launch_bounds__(160) void priors_kernel(
    const float* __restrict__ x, const float* __restrict__ Wt)
{
    extern __shared__ float sm[];
    float* sW = sm;                          // [NSLOT][RS*NI*NO]
    float* sX = sm + SMEM_X / 4;             // [NSLOT][NB][RS*NI]
    const unsigned smb  = sptr(sm);
    const unsigned mful = smb + SMEM_MBAR;         // full[j] = mful + 8j
    const unsigned memp = smb + SMEM_MBAR + 24;    // empty[j] = memp + 8j

    const int c  = blockIdx.y;
    const int r0 = blockIdx.x * RT;
    const int t  = threadIdx.x;

    if (t == 0) {
#pragma unroll
        for (int j = 0; j < NSLOT; j++) {
            mbar_init(mful + 8 * j, 1);     // completed by expect_tx + TMA
            mbar_init(memp + 8 * j, 4);     // 4 consumer-warp arrivals
        }
    }
    __syncthreads();                        // mbarriers visible to all

    if (t >= 128) {
        // ---------------- producer warp ----------------
        if (t == 128) {
            const u64t pol = mkpolicy_evict_first();
            int eph[NSLOT] = {1, 1, 1};     // first empty-wait passes
            for (int s = 0; s < NSTAGE; s++) {
                const int j = s % NSLOT;
                mbar_wait(memp + 8 * j, eph[j]);
                eph[j] ^= 1;
                const unsigned m = mful + 8 * j;
                mbar_expect(m, STAGE_BYTES);
                bulk_g2s_ef(smb + SMEM_W + j * 32768,
                            Wt + (size_t)(c * NR + r0 + s * RS) * (NI * NO),
                            32768, m, pol);
#pragma unroll
                for (int b = 0; b < NB; b++)
                    bulk_g2s_ef(smb + SMEM_X + j * 4096 + b * (RS * NI * 4),
                                x + (size_t)((b * NC + c) * NR + r0 + s * RS) * NI,
                                RS * NI * 4, m, pol);
            }
        }
        return;
    }

    // ---------------- consumer warps ----------------
    const int rj = t >> 6;
    const int bq = (t >> 4) & 3;
    const int og = t & 15;
    const int b0 = 2 * bq, b1 = 2 * bq + 1;
    const int lane0 = ((t & 31) == 0);

    int fph[NSLOT] = {0, 0, 0};
    float4 ms0 = make_float4(0.f, 0.f, 0.f, 0.f);
    float4 ms1 = make_float4(0.f, 0.f, 0.f, 0.f);

    for (int s = 0; s < NSTAGE; s++) {
        const int j = s % NSLOT;
        mbar_wait(mful + 8 * j, fph[j]);
        fph[j] ^= 1;

        const float*  Wb  = sW + j * (RS * NI * NO) + rj * (NI * NO);
        const float4* xr0 = (const float4*)(sX + j * (NB * RS * NI) + (b0 * RS + rj) * NI);
        const float4* xr1 = (const float4*)(sX + j * (NB * RS * NI) + (b1 * RS + rj) * NI);

        float4 a0 = make_float4(0.f, 0.f, 0.f, 0.f);
        float4 a1 = make_float4(0.f, 0.f, 0.f, 0.f);

#pragma unroll
        for (int i4 = 0; i4 < NI / 4; i4++) {
            float4 xv0 = xr0[i4];
            float4 xv1 = xr1[i4];
            const float4* wrow = (const float4*)(Wb + (i4 * 4) * NO) + og;
            float4 w0 = wrow[0];
            float4 w1 = wrow[16];
            float4 w2 = wrow[32];
            float4 w3 = wrow[48];
            FMA4(a0, xv0.x, w0); FMA4(a1, xv1.x, w0);
            FMA4(a0, xv0.y, w1); FMA4(a1, xv1.y, w1);
            FMA4(a0, xv0.z, w2); FMA4(a1, xv1.z, w2);
            FMA4(a0, xv0.w, w3); FMA4(a1, xv1.w, w3);
        }

        const int r = r0 + s * RS + rj;
        {
            union { uint2 u; __half2 h[2]; } pk;
            pk.h[0] = __floats2half2_rn(a0.x, a0.y);
            pk.h[1] = __floats2half2_rn(a0.z, a0.w);
            *(uint2*)(g_ph + (size_t)((b0 * NC + c) * NR + r) * NO + 4 * og) = pk.u;
            pk.h[0] = __floats2half2_rn(a1.x, a1.y);
            pk.h[1] = __floats2half2_rn(a1.z, a1.w);
            *(uint2*)(g_ph + (size_t)((b1 * NC + c) * NR + r) * NO + 4 * og) = pk.u;
        }

        ms0.x += a0.x; ms0.y += a0.y; ms0.z += a0.z; ms0.w += a0.w;
        ms1.x += a1.x; ms1.y += a1.y; ms1.z += a1.z; ms1.w += a1.w;

        __syncwarp();
        if (lane0) mbar_arrive(memp + 8 * j);   // this warp done with slot j
    }

    // iteration-0 fusion: sum_r priors -> g_pnum quarter 0
    float* d0 = g_pnum + (b0 * NC + c) * NO + 4 * og;
    float* d1 = g_pnum + (b1 * NC + c) * NO + 4 * og;
    atomicAdd(d0 + 0, ms0.x); atomicAdd(d0 + 1, ms0.y);
    atomicAdd(d0 + 2, ms0.z); atomicAdd(d0 + 3, ms0.w);
    atomicAdd(d1 + 0, ms1.x); atomicAdd(d1 + 1, ms1.y);
    atomicAdd(d1 + 2, ms1.z); atomicAdd(d1 + 3, ms1.w);
}

// ---------------------------------------------------------------------------
// Kernel 2: one routing iteration (branch-free: |w|<=2, |p|<~16 -> exp safe).
// Grid = NQ blocks per (b,c), 512 rows each; partials to scratch quarters.
// ---------------------------------------------------------------------------
__global__ __launch_bounds__(512) void iter_kernel()
{
    const int blk = blockIdx.x;
    const int bc  = blk >> 2;
    const int qq  = blk & 3;
    const int t   = threadIdx.x;
    const int o4  = t & 15;
    const int g   = t >> 4;

    const uint2* p2 = (const uint2*)(g_ph + (size_t)bc * NR * NO)
                      + (size_t)qq * (NR / NQ) * 16;
    const float4 wv = ((const float4*)g_w)[bc * 16 + o4];

    float d0 = 0.f, d1 = 0.f, d2 = 0.f, d3 = 0.f;
    float n0 = 0.f, n1 = 0.f, n2 = 0.f, n3 = 0.f;

#pragma unroll
    for (int k = 0; k < NR / NQ / 32; k++) {      // 16
        uint2 u = p2[(size_t)(g + 32 * k) * 16 + o4];
        float2 pa = __half22float2(*(__half2*)&u.x);
        float2 pb = __half22float2(*(__half2*)&u.y);
        float e;
        e = __expf(pa.x * wv.x); d0 += e; n0 += pa.x * e;
        e = __expf(pa.y * wv.y); d1 += e; n1 += pa.y * e;
        e = __expf(pb.x * wv.z); d2 += e; n2 += pb.x * e;
        e = __expf(pb.y * wv.w); d3 += e; n3 += pb.y * e;
    }

    __shared__ float smr[2][32][64];
    {
        int ob = o4 * 4;
        smr[0][g][ob + 0] = d0; smr[1][g][ob + 0] = n0;
        smr[0][g][ob + 1] = d1; smr[1][g][ob + 1] = n1;
        smr[0][g][ob + 2] = d2; smr[1][g][ob + 2] = n2;
        smr[0][g][ob + 3] = d3; smr[1][g][ob + 3] = n3;
    }
    __syncthreads();

    if (t < 64) {
        float D = 0.f, N = 0.f;
#pragma unroll 8
        for (int g2 = 0; g2 < 32; g2++) {
            D += smr[0][g2][t];
            N += smr[1][g2][t];
        }
        g_pden[qq * TOT + bc * NO + t] = D;
        g_pnum[qq * TOT + bc * NO + t] = N;
    }
}

// ---------------------------------------------------------------------------
// Kernel 3: s -> squash scale -> update w or write out.
// first=1: s = g_pnum[0]/2048 (uniform softmax, fused iteration 0).
// ---------------------------------------------------------------------------
__global__ __launch_bounds__(512) void squash_kernel(float* __restrict__ out,
                                                     int last, int first)
{
    const int t = threadIdx.x;

    float sv[32];
    float acc = 0.f;
#pragma unroll
    for (int q = 0; q < 32; q++) {
        int j = t + 512 * q;
        float s;
        if (first) {
            s = g_pnum[j] * (1.0f / (float)NR);
        } else {
            float D = g_pden[j] + g_pden[TOT + j] + g_pden[2 * TOT + j] + g_pden[3 * TOT + j];
            float N = g_pnum[j] + g_pnum[TOT + j] + g_pnum[2 * TOT + j] + g_pnum[3 * TOT + j];
            s = N / D;
        }
        sv[q] = s;
        acc += s * s;
    }

    __shared__ float red[16];
    __shared__ float s_scale;
#pragma unroll
    for (int off = 16; off > 0; off >>= 1)
        acc += __shfl_xor_sync(0xFFFFFFFFu, acc, off);
    if ((t & 31) == 0) red[t >> 5] = acc;
    __syncthreads();
    if (t < 32) {
        float a = (t < 16) ? red[t] : 0.f;
#pragma unroll
        for (int off = 8; off > 0; off >>= 1)
            a += __shfl_xor_sync(0xFFFFFFFFu, a, off);
        if (t == 0) s_scale = sqrtf(a) / (1.0f + a);
    }
    __syncthreads();
    const float sc = s_scale;

    if (last) {
#pragma unroll
        for (int q = 0; q < 32; q++) out[t + 512 * q] = sv[q] * sc;
    } else {
#pragma unroll
        for (int q = 0; q < 32; q++) g_w[t + 512 * q] += sv[q] * sc;
    }
}

// ---------------------------------------------------------------------------
extern "C" void kernel_launch(void* const* d_in, const int* in_sizes, int n_in,
                              void* d_out, int out_size)
{
    (void)in_sizes; (void)n_in; (void)out_size;
    const float* x  = (const float*)d_in[0];
    const float* Wt = (const float*)d_in[1];
    float* out = (float*)d_out;

    cudaFuncSetAttribute(priors_kernel,
                         cudaFuncAttributeMaxDynamicSharedMemorySize, SMEM_TOTAL);

    zero_kernel<<<32, 512>>>();
    priors_kernel<<<dim3(NR / RT, NC), 160, SMEM_TOTAL>>>(x, Wt);

    squash_kernel<<<1, 512>>>(nullptr, 0, 1);   // w = v0   (iteration 0, fused sum)

    iter_kernel<<<NQ * NB * NC, 512>>>();       // iteration 1
    squash_kernel<<<1, 512>>>(nullptr, 0, 0);   // w = v0 + v1

    iter_kernel<<<NQ * NB * NC, 512>>>();       // iteration 2
    squash_kernel<<<1, 512>>>(out, 1, 0);       // final squash -> output
}